// round 13
// baseline (speedup 1.0000x reference)
#include <cuda_runtime.h>

// BranchRoute: score = sigmoid(x @ gate_w + gate_b); mask_i = score_i > 0.5
// out = concat(x*m0, x*m1, x*(m0+m1)), each [N, D] fp32.
// sigmoid(z) > 0.5 <=> z > 0, so only the dot-product sign matters.
//
// R13: block-size sweep — the last untested knob (256 threads in all prior
// rounds). 128 threads/block, one row/block, grid=8192:
//  - 8 front-batched LDG.128 per thread (MLP_p1=8, 2x R11) -> each warp has
//    twice the outstanding DRAM reads.
//  - 24 STG.128 per thread -> longer uninterrupted per-warp store bursts.
//  - gate loads interleaved per-chunk (short live ranges, ~60 regs).
//  - 4-warp reduce (red[4]) instead of 8.
// Best so far: R11 (bench 85.2us, kernel 81.3us, DRAM 74.2%).

#define THREADS 128
#define DIM 4096
#define CHUNKS 8   // float4s per thread = 4096 / (128*4)

__global__ void __launch_bounds__(THREADS)
branch_route_kernel(const float* __restrict__ x,
                    const float* __restrict__ gw,   // [D, 2]
                    const float* __restrict__ gb,   // [2]
                    float* __restrict__ out,        // [3, N, D]
                    int N)
{
    const int t = threadIdx.x;
    const int row = blockIdx.x;

    // Front-batched DRAM loads: 8 x LDG.128 (MLP_p1 = 8).
    const float4* xr = (const float4*)(x + (size_t)row * DIM);
    float4 v[CHUNKS];
#pragma unroll
    for (int c = 0; c < CHUNKS; c++) v[c] = xr[c * THREADS + t];

    // Dot: per-chunk gate loads (2 x LDG.128 from L2) interleaved with FMAs,
    // keeping gate live-ranges short.
    const float4* gw4 = (const float4*)gw;   // 2 col-pairs per float4
    float s0 = 0.f, s1 = 0.f;
#pragma unroll
    for (int c = 0; c < CHUNKS; c++) {
        const int q = (c * THREADS + t) * 2;     // float4 index into gw
        const float4 wa = __ldg(&gw4[q + 0]);    // cols 4k+0, 4k+1
        const float4 wb = __ldg(&gw4[q + 1]);    // cols 4k+2, 4k+3
        s0 = fmaf(v[c].x, wa.x, s0);  s1 = fmaf(v[c].x, wa.y, s1);
        s0 = fmaf(v[c].y, wa.z, s0);  s1 = fmaf(v[c].y, wa.w, s1);
        s0 = fmaf(v[c].z, wb.x, s0);  s1 = fmaf(v[c].z, wb.y, s1);
        s0 = fmaf(v[c].w, wb.z, s0);  s1 = fmaf(v[c].w, wb.w, s1);
    }

    // Warp butterfly reduce.
#pragma unroll
    for (int o = 16; o > 0; o >>= 1) {
        s0 += __shfl_xor_sync(0xffffffffu, s0, o);
        s1 += __shfl_xor_sync(0xffffffffu, s1, o);
    }

    __shared__ __align__(16) float2 red[4];
    if ((t & 31) == 0) red[t >> 5] = make_float2(s0, s1);
    __syncthreads();

    float d0 = gb[0], d1 = gb[1];
#pragma unroll
    for (int k = 0; k < 2; k++) {
        const float4 r = ((const float4*)red)[k];   // two partials per LDS.128
        d0 += r.x + r.z;
        d1 += r.y + r.w;
    }

    const float f0 = d0 > 0.f ? 1.f : 0.f;
    const float f1 = d1 > 0.f ? 1.f : 0.f;
    const float fc = f0 + f1;

    const size_t base = (size_t)row * (DIM / 4);
    float4* __restrict__ p0 = (float4*)out + base;
    float4* __restrict__ p1 = (float4*)out + (size_t)N * (DIM / 4) + base;
    float4* __restrict__ pc = (float4*)out + (size_t)2 * N * (DIM / 4) + base;

#pragma unroll
    for (int c = 0; c < CHUNKS; c++) {
        const int idx = c * THREADS + t;
        float4 a, b, s;
        a.x = f0 * v[c].x; a.y = f0 * v[c].y; a.z = f0 * v[c].z; a.w = f0 * v[c].w;
        b.x = f1 * v[c].x; b.y = f1 * v[c].y; b.z = f1 * v[c].z; b.w = f1 * v[c].w;
        s.x = fc * v[c].x; s.y = fc * v[c].y; s.z = fc * v[c].z; s.w = fc * v[c].w;
        p0[idx] = a;
        p1[idx] = b;
        pc[idx] = s;
    }
}

extern "C" void kernel_launch(void* const* d_in, const int* in_sizes, int n_in,
                              void* d_out, int out_size)
{
    const float* x  = (const float*)d_in[0];
    const float* gw = (const float*)d_in[1];
    const float* gb = (const float*)d_in[2];
    float* out = (float*)d_out;

    const int N = in_sizes[0] / DIM;   // 8192

    // One row per block, 128 threads.
    branch_route_kernel<<<N, THREADS>>>(x, gw, gb, out, N);
}

// round 14
// speedup vs baseline: 1.0352x; 1.0352x over previous
#include <cuda_runtime.h>

// BranchRoute: score = sigmoid(x @ gate_w + gate_b); mask_i = score_i > 0.5
// out = concat(x*m0, x*m1, x*(m0+m1)), each [N, D] fp32.
// sigmoid(z) > 0.5 <=> z > 0, so only the dot-product sign matters.
//
// R14: complete the block-size curve (128: 72.0% DRAM, 256: 74.2% = best,
// 512: ?). One row per block, 512 threads, grid=8192. Per thread:
// 2x LDG.128 (x) + 4x LDG.128 (gate, L2) + 6x STG.128. ~32 regs -> higher
// residency; per-row reduce spread over 16 warps; finest store interleave.
// Best so far: R11 (bench 85.2us, kernel 81.3us, DRAM 74.2%).

#define THREADS 512
#define DIM 4096
#define CHUNKS 2   // float4s per thread = 4096 / (512*4)

__global__ void __launch_bounds__(THREADS)
branch_route_kernel(const float* __restrict__ x,
                    const float* __restrict__ gw,   // [D, 2]
                    const float* __restrict__ gb,   // [2]
                    float* __restrict__ out,        // [3, N, D]
                    int N)
{
    const int t = threadIdx.x;
    const int row = blockIdx.x;

    // Gate pairs for this thread's 8 columns: 4 x LDG.128 (L2-resident).
    // Thread owns columns {c*2048 + 4t + j : c in 0..1, j in 0..3}.
    float4 wv[4];
    {
        const float4* gw4 = (const float4*)gw;   // 2 col-pairs per float4
#pragma unroll
        for (int c = 0; c < CHUNKS; c++) {
            const int q = (c * 2048 + t * 4) >> 1;   // float4 index
            wv[c * 2 + 0] = __ldg(&gw4[q + 0]);      // cols 4t+0, 4t+1
            wv[c * 2 + 1] = __ldg(&gw4[q + 1]);      // cols 4t+2, 4t+3
        }
    }

    // Row chunk: 2 x LDG.128.
    const float4* xr = (const float4*)(x + (size_t)row * DIM);
    float4 v[CHUNKS];
#pragma unroll
    for (int c = 0; c < CHUNKS; c++) v[c] = xr[c * THREADS + t];

    // Partial dots.
    float s0 = 0.f, s1 = 0.f;
#pragma unroll
    for (int c = 0; c < CHUNKS; c++) {
        const float4 wa = wv[c * 2 + 0];
        const float4 wb = wv[c * 2 + 1];
        s0 = fmaf(v[c].x, wa.x, s0);  s1 = fmaf(v[c].x, wa.y, s1);
        s0 = fmaf(v[c].y, wa.z, s0);  s1 = fmaf(v[c].y, wa.w, s1);
        s0 = fmaf(v[c].z, wb.x, s0);  s1 = fmaf(v[c].z, wb.y, s1);
        s0 = fmaf(v[c].w, wb.z, s0);  s1 = fmaf(v[c].w, wb.w, s1);
    }

    // Warp butterfly reduce.
#pragma unroll
    for (int o = 16; o > 0; o >>= 1) {
        s0 += __shfl_xor_sync(0xffffffffu, s0, o);
        s1 += __shfl_xor_sync(0xffffffffu, s1, o);
    }

    __shared__ __align__(16) float2 red[16];
    if ((t & 31) == 0) red[t >> 5] = make_float2(s0, s1);
    __syncthreads();

    float d0 = gb[0], d1 = gb[1];
#pragma unroll
    for (int k = 0; k < 8; k++) {
        const float4 r = ((const float4*)red)[k];   // two partials per LDS.128
        d0 += r.x + r.z;
        d1 += r.y + r.w;
    }

    const float f0 = d0 > 0.f ? 1.f : 0.f;
    const float f1 = d1 > 0.f ? 1.f : 0.f;
    const float fc = f0 + f1;

    const size_t base = (size_t)row * (DIM / 4);
    float4* __restrict__ p0 = (float4*)out + base;
    float4* __restrict__ p1 = (float4*)out + (size_t)N * (DIM / 4) + base;
    float4* __restrict__ pc = (float4*)out + (size_t)2 * N * (DIM / 4) + base;

#pragma unroll
    for (int c = 0; c < CHUNKS; c++) {
        const int idx = c * THREADS + t;
        float4 a, b, s;
        a.x = f0 * v[c].x; a.y = f0 * v[c].y; a.z = f0 * v[c].z; a.w = f0 * v[c].w;
        b.x = f1 * v[c].x; b.y = f1 * v[c].y; b.z = f1 * v[c].z; b.w = f1 * v[c].w;
        s.x = fc * v[c].x; s.y = fc * v[c].y; s.z = fc * v[c].z; s.w = fc * v[c].w;
        p0[idx] = a;
        p1[idx] = b;
        pc[idx] = s;
    }
}

extern "C" void kernel_launch(void* const* d_in, const int* in_sizes, int n_in,
                              void* d_out, int out_size)
{
    const float* x  = (const float*)d_in[0];
    const float* gw = (const float*)d_in[1];
    const float* gb = (const float*)d_in[2];
    float* out = (float*)d_out;

    const int N = in_sizes[0] / DIM;   // 8192

    // One row per block, 512 threads.
    branch_route_kernel<<<N, THREADS>>>(x, gw, gb, out, N);
}